// round 13
// baseline (speedup 1.0000x reference)
#include <cuda_runtime.h>
#include <cuda_bf16.h>
#include <math.h>
#include <stdint.h>

#define B_TOT   262144
#define THREADS 256
#define CTAS    (B_TOT/THREADS)   // 1024

// ---- SMEM layout (bytes) ----
#define W2H_O   0        // W2 g1-folded hi: 128 rows x 272 B
#define W2L_O   34816    // W2 lo
#define W1H_O   69632    // W1 (+b1 row 28) hi: 32 rows x 272 B
#define W1L_O   78336    // W1 lo
#define W3H_O   87040    // W3 g2-folded hi: 128 rows x 16 B
#define W3L_O   89088    // W3 lo
#define G2C2_O  91136    // float2[128]
#define G3_O    92160    // 8 f
#define C3_O    92192    // 8 f
#define H1H_O   92224    // h1/v hi: 256 rows x 272 B (x staging overlay)
#define H1L_O   161856   // h1/v lo (S overlay in rows 0..3 per warp slot)
#define SMEM_BYTES 231488

typedef unsigned long long u64;

static __device__ __forceinline__ u64 pk2(float lo, float hi) {
    u64 r; asm("mov.b64 %0,{%1,%2};" : "=l"(r) : "f"(lo), "f"(hi)); return r;
}
static __device__ __forceinline__ void upk2(u64 v, float &lo, float &hi) {
    asm("mov.b64 {%0,%1},%2;" : "=f"(lo), "=f"(hi) : "l"(v));
}
static __device__ __forceinline__ u64 ffma2(u64 a, u64 b, u64 c) {
    u64 d; asm("fma.rn.f32x2 %0,%1,%2,%3;" : "=l"(d) : "l"(a), "l"(b), "l"(c)); return d;
}
static __device__ __forceinline__ u64 fadd2(u64 a, u64 b) {
    u64 d; asm("add.rn.f32x2 %0,%1,%2;" : "=l"(d) : "l"(a), "l"(b)); return d;
}
static __device__ __forceinline__ float gelu_exact(float x) {
    return 0.5f * x * (1.0f + erff(x * 0.70710678118654752f));
}
static __device__ __forceinline__ uint32_t s2u(const void* p){
    uint32_t a; asm("{ .reg .u64 t; cvta.to.shared.u64 t, %1; cvt.u32.u64 %0, t; }":"=r"(a):"l"(p)); return a;
}
static __device__ __forceinline__ void ldsm4(uint32_t& r0,uint32_t& r1,uint32_t& r2,uint32_t& r3, uint32_t a){
    asm volatile("ldmatrix.sync.aligned.m8n8.x4.shared.b16 {%0,%1,%2,%3}, [%4];"
        : "=r"(r0),"=r"(r1),"=r"(r2),"=r"(r3) : "r"(a));
}
static __device__ __forceinline__ void ldsm4t(uint32_t& r0,uint32_t& r1,uint32_t& r2,uint32_t& r3, uint32_t a){
    asm volatile("ldmatrix.sync.aligned.m8n8.x4.trans.shared.b16 {%0,%1,%2,%3}, [%4];"
        : "=r"(r0),"=r"(r1),"=r"(r2),"=r"(r3) : "r"(a));
}
static __device__ __forceinline__ void ldsm2t(uint32_t& r0,uint32_t& r1, uint32_t a){
    asm volatile("ldmatrix.sync.aligned.m8n8.x2.trans.shared.b16 {%0,%1}, [%2];"
        : "=r"(r0),"=r"(r1) : "r"(a));
}
static __device__ __forceinline__ void mma16816(float* d, const uint32_t* a, uint32_t b0, uint32_t b1){
    asm volatile("mma.sync.aligned.m16n8k16.row.col.f32.bf16.bf16.f32 "
        "{%0,%1,%2,%3}, {%4,%5,%6,%7}, {%8,%9}, {%0,%1,%2,%3};"
        : "+f"(d[0]),"+f"(d[1]),"+f"(d[2]),"+f"(d[3])
        : "r"(a[0]),"r"(a[1]),"r"(a[2]),"r"(a[3]), "r"(b0),"r"(b1));
}

#define FKJ(F00,F01,F02,F10,F11,F12,F20,F21,F22,PX,PY,PZ,TH) do {              \
    float s_, c_; __sincosf((TH), &s_, &c_);                                   \
    tx += r00*(PX) + r01*(PY) + r02*(PZ);                                      \
    ty += r10*(PX) + r11*(PY) + r12*(PZ);                                      \
    tz += r20*(PX) + r21*(PY) + r22*(PZ);                                      \
    float A0 = r00*(F00) + r01*(F10) + r02*(F20);                              \
    float A1 = r10*(F00) + r11*(F10) + r12*(F20);                              \
    float A2 = r20*(F00) + r21*(F10) + r22*(F20);                              \
    float B0 = r00*(F01) + r01*(F11) + r02*(F21);                              \
    float B1 = r10*(F01) + r11*(F11) + r12*(F21);                              \
    float B2 = r20*(F01) + r21*(F11) + r22*(F21);                              \
    float C0 = r00*(F02) + r01*(F12) + r02*(F22);                              \
    float C1 = r10*(F02) + r11*(F12) + r12*(F22);                              \
    float C2v = r20*(F02) + r21*(F12) + r22*(F22);                             \
    r00 = c_*A0 + s_*B0;  r01 = c_*B0 - s_*A0;  r02 = C0;                      \
    r10 = c_*A1 + s_*B1;  r11 = c_*B1 - s_*A1;  r12 = C1;                      \
    r20 = c_*A2 + s_*B2;  r21 = c_*B2 - s_*A2;  r22 = C2v;                     \
} while (0)

static __device__ __forceinline__ void front_sample(
    int s, int it, const float* th, float vm,
    const float* __restrict__ tgt2d, const float* __restrict__ camK,
    const float* __restrict__ Rext,  const float* __restrict__ text,
    float* __restrict__ outAllKp, float* __restrict__ outKp,
    float* __restrict__ outTheta, u64* xp, int last)
{
    float kx[7], ky[7], kz[7];
    float r00=1.f,r01=0.f,r02=0.f, r10=0.f,r11=1.f,r12=0.f, r20=0.f,r21=0.f,r22=1.f;
    float tx=0.f, ty=0.f, tz=0.f;
    FKJ(1,0,0,  0,1,0,  0,0,1,   0.f,      0.f,     0.333f, th[0]);
    FKJ(1,0,0,  0,0,1,  0,-1,0,  0.f,      0.f,     0.f,    th[1]);
    kx[1]=tx; ky[1]=ty; kz[1]=tz;
    FKJ(1,0,0,  0,0,-1, 0,1,0,   0.f,     -0.316f,  0.f,    th[2]);
    kx[2]=tx; ky[2]=ty; kz[2]=tz;
    FKJ(1,0,0,  0,0,-1, 0,1,0,   0.0825f,  0.f,     0.f,    th[3]);
    kx[3]=tx; ky[3]=ty; kz[3]=tz;
    FKJ(1,0,0,  0,0,1,  0,-1,0, -0.0825f,  0.384f,  0.f,    th[4]);
    FKJ(1,0,0,  0,0,-1, 0,1,0,   0.f,      0.f,     0.f,    th[5]);
    kx[4]=tx; ky[4]=ty; kz[4]=tz;
    FKJ(1,0,0,  0,0,-1, 0,1,0,   0.088f,   0.f,     0.f,    th[6]);
    kx[5]=tx; ky[5]=ty; kz[5]=tz;
    kx[6]=tx + 0.107f*r02; ky[6]=ty + 0.107f*r12; kz[6]=tz + 0.107f*r22;
    kx[0]=0.f; ky[0]=0.f; kz[0]=0.f;
    {
        float* p = outAllKp + ((size_t)it * B_TOT + s) * 21;
#pragma unroll
        for (int k = 0; k < 7; k++) { p[3*k]=kx[k]; p[3*k+1]=ky[k]; p[3*k+2]=kz[k]; }
    }
    if (last) {
#pragma unroll
        for (int jj = 0; jj < 7; jj++) outTheta[(size_t)s*7 + jj] = th[jj];
        float* pkf = outKp + (size_t)s*21;
#pragma unroll
        for (int k = 0; k < 7; k++) { pkf[3*k]=kx[k]; pkf[3*k+1]=ky[k]; pkf[3*k+2]=kz[k]; }
        return;
    }
    float re[9], Kc[9], te[3];
#pragma unroll
    for (int i = 0; i < 9; i++) { re[i] = Rext[(size_t)s*9+i]; Kc[i] = camK[(size_t)s*9+i]; }
#pragma unroll
    for (int i = 0; i < 3; i++) te[i] = text[(size_t)s*3+i];
    float dmag[7];
#pragma unroll
    for (int k = 0; k < 7; k++) {
        float cxm = re[0]*kx[k] + re[1]*ky[k] + re[2]*kz[k] + te[0];
        float cym = re[3]*kx[k] + re[4]*ky[k] + re[5]*kz[k] + te[1];
        float czm = re[6]*kx[k] + re[7]*ky[k] + re[8]*kz[k] + te[2];
        float iz = 1.0f / fmaxf(czm, 1e-6f);
        float nx = cxm*iz, ny = cym*iz, nz = czm*iz;
        float u = Kc[0]*nx + Kc[1]*ny + Kc[2]*nz;
        float v = Kc[3]*nx + Kc[4]*ny + Kc[5]*nz;
        float du = (tgt2d[(size_t)s*14 + 2*k    ] - u) * vm;
        float dv = (tgt2d[(size_t)s*14 + 2*k + 1] - v) * vm;
        xp[k] = pk2(du, dv);
        dmag[k] = sqrtf(du*du + dv*dv);
    }
    xp[7]  = pk2(th[0], th[1]);   xp[8]  = pk2(th[2], th[3]);
    xp[9]  = pk2(th[4], th[5]);   xp[10] = pk2(th[6], dmag[0]);
    xp[11] = pk2(dmag[1], dmag[2]); xp[12] = pk2(dmag[3], dmag[4]);
    xp[13] = pk2(dmag[5], dmag[6]);
}

__global__ __launch_bounds__(THREADS,1)
void irm_kernel(const float* __restrict__ ang0,  const float* __restrict__ tgt2d,
                const float* __restrict__ camK,  const float* __restrict__ Rext,
                const float* __restrict__ text,  const int* __restrict__ vmask,
                const float* __restrict__ W1,    const float* __restrict__ b1,
                const float* __restrict__ g1,    const float* __restrict__ be1,
                const float* __restrict__ W2,    const float* __restrict__ b2,
                const float* __restrict__ g2,    const float* __restrict__ be2,
                const float* __restrict__ W3,    const float* __restrict__ b3,
                const float* __restrict__ slog,  float* __restrict__ out)
{
    extern __shared__ float smf[];
    char* const smc = (char*)smf;
    const uint32_t sbase = s2u(smc);
    const int tid = threadIdx.x;
    const int wid = tid >> 5, lane = tid & 31;

    // ================= weight preprocessing =================
    for (int idx = tid; idx < 16384; idx += THREADS) {
        int k = idx >> 7, j = idx & 127;
        float v = g1[k] * W2[k*128 + j];
        __nv_bfloat16 h = __float2bfloat16(v);
        __nv_bfloat16 l = __float2bfloat16(v - __bfloat162float(h));
        *(__nv_bfloat16*)(smc + W2H_O + k*272 + j*2) = h;
        *(__nv_bfloat16*)(smc + W2L_O + k*272 + j*2) = l;
    }
    for (int idx = tid; idx < 4096; idx += THREADS) {
        int k = idx >> 7, j = idx & 127;
        float v = (k < 28) ? W1[k*128 + j] : ((k == 28) ? b1[j] : 0.f);
        __nv_bfloat16 h = __float2bfloat16(v);
        __nv_bfloat16 l = __float2bfloat16(v - __bfloat162float(h));
        *(__nv_bfloat16*)(smc + W1H_O + k*272 + j*2) = h;
        *(__nv_bfloat16*)(smc + W1L_O + k*272 + j*2) = l;
    }
    // W3 (g2-folded) bf16 hi/lo: 128 k-rows x 8 cols (col 7 zero-pad), 16B rows
    for (int idx = tid; idx < 1024; idx += THREADS) {
        int k = idx >> 3, jj = idx & 7;
        float v = (jj < 7) ? g2[k] * W3[k*7 + jj] : 0.f;
        __nv_bfloat16 h = __float2bfloat16(v);
        __nv_bfloat16 l = __float2bfloat16(v - __bfloat162float(h));
        *(__nv_bfloat16*)(smc + W3H_O + k*16 + jj*2) = h;
        *(__nv_bfloat16*)(smc + W3L_O + k*16 + jj*2) = l;
    }
    if (tid < 128) {
        float ga = 0.f, ca = 0.f;
        for (int k = 0; k < 128; k++) { float w = W2[k*128 + tid]; ga += g1[k]*w; ca += be1[k]*w; }
        ((float2*)(smc + G2C2_O))[tid] = make_float2(ga, ca + b2[tid]);
    }
    if (tid < 8) {
        float ga = 0.f, ca = 0.f;
        if (tid < 7) {
            for (int k = 0; k < 128; k++) { float w = W3[k*7 + tid]; ga += g2[k]*w; ca += be2[k]*w; }
            ca += b3[tid];
        }
        ((float*)(smc + G3_O))[tid] = ga;  ((float*)(smc + C3_O))[tid] = ca;
    }
    __syncthreads();

    // ================= per-thread sample =================
    const int s = blockIdx.x * THREADS + tid;
    float th[7];
#pragma unroll
    for (int j = 0; j < 7; j++) th[j] = ang0[s*7 + j];
    const float vm = (vmask[s] != 0) ? 1.0f : 0.0f;

    float* const outTheta = out;
    float* const outKp    = out + (size_t)B_TOT*7;
    float* const outAng   = out + (size_t)B_TOT*28;
    float* const outAllKp = out + (size_t)B_TOT*56;
#pragma unroll
    for (int j = 0; j < 7; j++) outAng[(size_t)s*7 + j] = th[j];

    // fragment geometry
    const int lidx = lane >> 3, lr = lane & 7;
    const int dm = lane >> 2, q = lane & 3;
    const uint32_t frag272 = (uint32_t)(((lidx & 1)*8 + lr)*272 + (lidx >> 1)*16);
    const uint32_t frag80  = (uint32_t)(((lidx & 1)*8 + lr)*80  + (lidx >> 1)*16);
    const uint32_t wslot   = (uint32_t)wid * 8704u;
    const uint32_t xAddrH  = sbase + H1H_O + wslot + frag80;
    const uint32_t aAddr0  = sbase + H1H_O + wslot + frag272;
    const uint32_t aAddr1  = aAddr0 + 16u*272u;
    const uint32_t w1Addr  = sbase + W1H_O + frag272;
    const uint32_t bAddr   = sbase + W2H_O + frag272;
    const uint32_t w3Addr  = sbase + W3H_O + (uint32_t)(lane & 15)*16u;
    char* const sSlot      = smc + H1L_O + wslot;      // S overlay (rows 0..3 of v-lo)
    const int dj  = 2*q;

    for (int it = 0; it < 4; ++it) {
        u64 xp[14];
        const int last = (it == 3);
        front_sample(s, it, th, vm, tgt2d, camK, Rext, text, outAllKp, outKp, outTheta, xp, last);
        if (last) break;

        // ---------------- stage x (bf16 hi/lo) into per-warp slot ----------------
        {
            uint32_t xh[16], xl[16];
#pragma unroll
            for (int c = 0; c < 14; c++) {
                float v0, v1; upk2(xp[c], v0, v1);
                __nv_bfloat162 H = __floats2bfloat162_rn(v0, v1);
                __nv_bfloat162 L = __floats2bfloat162_rn(v0 - __low2float(H), v1 - __high2float(H));
                xh[c] = *(uint32_t*)&H;  xl[c] = *(uint32_t*)&L;
            }
            __nv_bfloat162 Hb = __floats2bfloat162_rn(1.0f, 0.0f);
            xh[14] = *(uint32_t*)&Hb;  xl[14] = 0u;  xh[15] = 0u;  xl[15] = 0u;
            char* px = smc + H1H_O + wslot + lane*80;
            *(uint4*)(px)      = make_uint4(xh[0],xh[1],xh[2],xh[3]);
            *(uint4*)(px + 16) = make_uint4(xh[4],xh[5],xh[6],xh[7]);
            *(uint4*)(px + 32) = make_uint4(xh[8],xh[9],xh[10],xh[11]);
            *(uint4*)(px + 48) = make_uint4(xh[12],xh[13],xh[14],xh[15]);
            char* pl = px + (H1L_O - H1H_O);
            *(uint4*)(pl)      = make_uint4(xl[0],xl[1],xl[2],xl[3]);
            *(uint4*)(pl + 16) = make_uint4(xl[4],xl[5],xl[6],xl[7]);
            *(uint4*)(pl + 32) = make_uint4(xl[8],xl[9],xl[10],xl[11]);
            *(uint4*)(pl + 48) = make_uint4(xl[12],xl[13],xl[14],xl[15]);
        }
        __syncwarp();

        // ---------------- MMA1: h1pre = x @ W1 (+bias row) ----------------
        uint32_t a1h[2][2][4], a1l[2][2][4];
#pragma unroll
        for (int st = 0; st < 2; st++)
#pragma unroll
            for (int ks = 0; ks < 2; ks++) {
                uint32_t base = xAddrH + st*1280 + ks*32;
                ldsm4(a1h[st][ks][0],a1h[st][ks][1],a1h[st][ks][2],a1h[st][ks][3], base);
                ldsm4(a1l[st][ks][0],a1l[st][ks][1],a1l[st][ks][2],a1l[st][ks][3], base + (H1L_O - H1H_O));
            }

        u64 sP[2][2] = {{0,0},{0,0}}, qP[2][2] = {{0,0},{0,0}};
        float rs1v[2][2], bc1v[2][2];

        for (int nh = 0; nh < 2; nh++) {
            float acc1[2][8][4];
#pragma unroll
            for (int st2 = 0; st2 < 2; st2++)
#pragma unroll
                for (int t = 0; t < 8; t++)
#pragma unroll
                    for (int e = 0; e < 4; e++) acc1[st2][t][e] = 0.f;
#pragma unroll
            for (int ks = 0; ks < 2; ks++)
#pragma unroll
                for (int gl = 0; gl < 4; gl++) {
                    uint32_t ba = w1Addr + (uint32_t)ks*4352u + (uint32_t)(nh*4+gl)*32u;
                    uint32_t bh0,bh1,bh2,bh3, bl0,bl1,bl2,bl3;
                    ldsm4t(bh0,bh1,bh2,bh3, ba);
                    ldsm4t(bl0,bl1,bl2,bl3, ba + (W1L_O - W1H_O));
#pragma unroll
                    for (int st2 = 0; st2 < 2; st2++) {
                        mma16816(acc1[st2][2*gl],   a1h[st2][ks], bh0, bh1);
                        mma16816(acc1[st2][2*gl],   a1l[st2][ks], bh0, bh1);
                        mma16816(acc1[st2][2*gl],   a1h[st2][ks], bl0, bl1);
                        mma16816(acc1[st2][2*gl+1], a1h[st2][ks], bh2, bh3);
                        mma16816(acc1[st2][2*gl+1], a1l[st2][ks], bh2, bh3);
                        mma16816(acc1[st2][2*gl+1], a1h[st2][ks], bl2, bl3);
                    }
                }
            // epi1: GELU on fragments, LN1 stats, h1 -> SMEM (bf16 hi/lo)
#pragma unroll
            for (int st2 = 0; st2 < 2; st2++)
#pragma unroll
                for (int t = 0; t < 8; t++) {
                    float v0 = gelu_exact(acc1[st2][t][0]);
                    float v1 = gelu_exact(acc1[st2][t][1]);
                    float v2 = gelu_exact(acc1[st2][t][2]);
                    float v3 = gelu_exact(acc1[st2][t][3]);
                    u64 p01 = pk2(v0,v1), p23 = pk2(v2,v3);
                    sP[st2][0] = fadd2(sP[st2][0], p01);
                    qP[st2][0] = ffma2(p01, p01, qP[st2][0]);
                    sP[st2][1] = fadd2(sP[st2][1], p23);
                    qP[st2][1] = ffma2(p23, p23, qP[st2][1]);
                    __nv_bfloat162 H0 = __floats2bfloat162_rn(v0, v1);
                    __nv_bfloat162 L0 = __floats2bfloat162_rn(v0 - __low2float(H0), v1 - __high2float(H0));
                    __nv_bfloat162 H1 = __floats2bfloat162_rn(v2, v3);
                    __nv_bfloat162 L1 = __floats2bfloat162_rn(v2 - __low2float(H1), v3 - __high2float(H1));
                    uint32_t colb = (uint32_t)(((nh*8 + t)*8 + dj)*2);
                    char* r0p = smc + H1H_O + wslot + (uint32_t)(st2*16 + dm)*272u + colb;
                    char* r1p = smc + H1H_O + wslot + (uint32_t)(st2*16 + dm + 8)*272u + colb;
                    *(uint32_t*)r0p = *(uint32_t*)&H0;
                    *(uint32_t*)r1p = *(uint32_t*)&H1;
                    *(uint32_t*)(r0p + (H1L_O - H1H_O)) = *(uint32_t*)&L0;
                    *(uint32_t*)(r1p + (H1L_O - H1H_O)) = *(uint32_t*)&L1;
                }
        }
        __syncwarp();

        // LN1 stats finalize (fragment-row domain; no thread broadcast needed)
#pragma unroll
        for (int st2 = 0; st2 < 2; st2++)
#pragma unroll
            for (int h = 0; h < 2; h++) {
                float a, b; upk2(sP[st2][h], a, b); float sum = a + b;
                upk2(qP[st2][h], a, b); float sq = a + b;
                sum += __shfl_xor_sync(0xFFFFFFFFu, sum, 1);
                sum += __shfl_xor_sync(0xFFFFFFFFu, sum, 2);
                sq  += __shfl_xor_sync(0xFFFFFFFFu, sq, 1);
                sq  += __shfl_xor_sync(0xFFFFFFFFu, sq, 2);
                float mu = sum * (1.0f/128.0f);
                float rs = rsqrtf(sq*(1.0f/128.0f) - mu*mu + 1e-5f);
                rs1v[st2][h] = rs;  bc1v[st2][h] = rs*mu;
            }

        // ---------------- MMA2: h2pre = h1 @ W2g ----------------
        float acc[2][16][4];
#pragma unroll
        for (int st2 = 0; st2 < 2; st2++)
#pragma unroll
            for (int t = 0; t < 16; t++)
#pragma unroll
                for (int e = 0; e < 4; e++) acc[st2][t][e] = 0.f;

        for (int ks = 0; ks < 8; ks++) {
            uint32_t ah[2][4], al[2][4];
            ldsm4(ah[0][0],ah[0][1],ah[0][2],ah[0][3], aAddr0 + ks*32);
            ldsm4(al[0][0],al[0][1],al[0][2],al[0][3], aAddr0 + ks*32 + (H1L_O - H1H_O));
            ldsm4(ah[1][0],ah[1][1],ah[1][2],ah[1][3], aAddr1 + ks*32);
            ldsm4(al[1][0],al[1][1],al[1][2],al[1][3], aAddr1 + ks*32 + (H1L_O - H1H_O));
#pragma unroll
            for (int jt2 = 0; jt2 < 8; jt2++) {
                uint32_t bh0,bh1,bh2,bh3, bl0,bl1,bl2,bl3;
                uint32_t ba = bAddr + (uint32_t)ks*16u*272u + (uint32_t)jt2*32u;
                ldsm4t(bh0,bh1,bh2,bh3, ba);
                ldsm4t(bl0,bl1,bl2,bl3, ba + (W2L_O - W2H_O));
#pragma unroll
                for (int st2 = 0; st2 < 2; st2++) {
                    mma16816(acc[st2][2*jt2],   ah[st2], bh0, bh1);
                    mma16816(acc[st2][2*jt2],   al[st2], bh0, bh1);
                    mma16816(acc[st2][2*jt2],   ah[st2], bl0, bl1);
                    mma16816(acc[st2][2*jt2+1], ah[st2], bh2, bh3);
                    mma16816(acc[st2][2*jt2+1], al[st2], bh2, bh3);
                    mma16816(acc[st2][2*jt2+1], ah[st2], bl2, bl3);
                }
            }
        }
        __syncwarp();   // all h1 ldsm reads done before v overwrites rows

        // ---------------- epi-2 (fragment domain): LN1-fold -> GELU -> LN2 stats, v -> SMEM ----------------
        u64 s2P[2][2] = {{0,0},{0,0}}, q2P[2][2] = {{0,0},{0,0}};
#pragma unroll
        for (int t = 0; t < 16; t++) {
            float4 g = *(const float4*)(smc + G2C2_O + (uint32_t)(t*8 + dj)*8u);
#pragma unroll
            for (int st2 = 0; st2 < 2; st2++) {
                float v0 = gelu_exact(rs1v[st2][0]*acc[st2][t][0] - bc1v[st2][0]*g.x + g.y);
                float v1 = gelu_exact(rs1v[st2][0]*acc[st2][t][1] - bc1v[st2][0]*g.z + g.w);
                float v2 = gelu_exact(rs1v[st2][1]*acc[st2][t][2] - bc1v[st2][1]*g.x + g.y);
                float v3 = gelu_exact(rs1v[st2][1]*acc[st2][t][3] - bc1v[st2][1]*g.z + g.w);
                u64 p01 = pk2(v0,v1), p23 = pk2(v2,v3);
                s2P[st2][0] = fadd2(s2P[st2][0], p01);
                q2P[st2][0] = ffma2(p01, p01, q2P[st2][0]);
                s2P[st2][1] = fadd2(s2P[st2][1], p23);
                q2P[st2][1] = ffma2(p23, p23, q2P[st2][1]);
                __nv_bfloat162 H0 = __floats2bfloat162_rn(v0, v1);
                __nv_bfloat162 L0 = __floats2bfloat162_rn(v0 - __low2float(H0), v1 - __high2float(H0));
                __nv_bfloat162 H1 = __floats2bfloat162_rn(v2, v3);
                __nv_bfloat162 L1 = __floats2bfloat162_rn(v2 - __low2float(H1), v3 - __high2float(H1));
                uint32_t colb = (uint32_t)((t*8 + dj)*2);
                char* r0p = smc + H1H_O + wslot + (uint32_t)(st2*16 + dm)*272u + colb;
                char* r1p = smc + H1H_O + wslot + (uint32_t)(st2*16 + dm + 8)*272u + colb;
                *(uint32_t*)r0p = *(uint32_t*)&H0;
                *(uint32_t*)r1p = *(uint32_t*)&H1;
                *(uint32_t*)(r0p + (H1L_O - H1H_O)) = *(uint32_t*)&L0;
                *(uint32_t*)(r1p + (H1L_O - H1H_O)) = *(uint32_t*)&L1;
            }
        }
        __syncwarp();

        // LN2 stats finalize
        float rs2v[2][2], bc2v[2][2];
#pragma unroll
        for (int st2 = 0; st2 < 2; st2++)
#pragma unroll
            for (int h = 0; h < 2; h++) {
                float a, b; upk2(s2P[st2][h], a, b); float sum = a + b;
                upk2(q2P[st2][h], a, b); float sq = a + b;
                sum += __shfl_xor_sync(0xFFFFFFFFu, sum, 1);
                sum += __shfl_xor_sync(0xFFFFFFFFu, sum, 2);
                sq  += __shfl_xor_sync(0xFFFFFFFFu, sq, 1);
                sq  += __shfl_xor_sync(0xFFFFFFFFu, sq, 2);
                float mu = sum * (1.0f/128.0f);
                float rs = rsqrtf(sq*(1.0f/128.0f) - mu*mu + 1e-5f);
                rs2v[st2][h] = rs;  bc2v[st2][h] = rs*mu;
            }

        // ---------------- MMA3: S = v @ W3g (n=8) ----------------
        float acc3[2][4] = {{0,0,0,0},{0,0,0,0}};
        for (int ks = 0; ks < 8; ks++) {
            uint32_t ah[2][4], al[2][4];
            ldsm4(ah[0][0],ah[0][1],ah[0][2],ah[0][3], aAddr0 + ks*32);
            ldsm4(al[0][0],al[0][1],al[0][2],al[0][3], aAddr0 + ks*32 + (H1L_O - H1H_O));
            ldsm4(ah[1][0],ah[1][1],ah[1][2],ah[1][3], aAddr1 + ks*32);
            ldsm4(al[1][0],al[1][1],al[1][2],al[1][3], aAddr1 + ks*32 + (H1L_O - H1H_O));
            uint32_t b0h,b1h, b0l,b1l;
            ldsm2t(b0h,b1h, w3Addr + (uint32_t)ks*256u);
            ldsm2t(b0l,b1l, w3Addr + (uint32_t)ks*256u + (W3L_O - W3H_O));
#pragma unroll
            for (int st2 = 0; st2 < 2; st2++) {
                mma16816(acc3[st2], ah[st2], b0h, b1h);
                mma16816(acc3[st2], al[st2], b0h, b1h);
                mma16816(acc3[st2], ah[st2], b0l, b1l);
            }
        }
        __syncwarp();   // all v-lo ldsm reads done before S overlays rows 0..3

        // S store: per-warp region, row = sample-in-warp, 32 B each
#pragma unroll
        for (int st2 = 0; st2 < 2; st2++) {
            *(float2*)(sSlot + (uint32_t)(st2*16 + dm)*32u + q*8u)     = make_float2(acc3[st2][0], acc3[st2][1]);
            *(float2*)(sSlot + (uint32_t)(st2*16 + dm + 8)*32u + q*8u) = make_float2(acc3[st2][2], acc3[st2][3]);
        }
        __syncwarp();

        // read own sample's S row + rs2 broadcast + theta update
        float4 Sa = *(const float4*)(sSlot + (uint32_t)lane*32u);
        float4 Sb = *(const float4*)(sSlot + (uint32_t)lane*32u + 16u);
        float Sv[8] = {Sa.x,Sa.y,Sa.z,Sa.w, Sb.x,Sb.y,Sb.z,Sb.w};
        float rs2 = 0.f, bco2 = 0.f;
        {
            const int st_s = lane >> 4, h_s = (lane >> 3) & 1, src = (lane & 7)*4;
#pragma unroll
            for (int st2 = 0; st2 < 2; st2++)
#pragma unroll
                for (int h = 0; h < 2; h++) {
                    float tr = __shfl_sync(0xFFFFFFFFu, rs2v[st2][h], src);
                    float tb = __shfl_sync(0xFFFFFFFFu, bc2v[st2][h], src);
                    if (st2 == st_s && h == h_s) { rs2 = tr; bco2 = tb; }
                }
        }
        const float* G3f = (const float*)(smc + G3_O);
        const float* C3f = (const float*)(smc + C3_O);
        const float ssi = 1.0f/(1.0f + expf(-slog[it]));
        const float LO[7] = {-2.8973f,-1.7628f,-2.8973f,-3.0718f,-2.8973f,-0.0175f,-2.8973f};
        const float HI[7] = { 2.8973f, 1.7628f, 2.8973f,-0.0698f, 2.8973f, 3.7525f, 2.8973f};
#pragma unroll
        for (int jj = 0; jj < 7; jj++) {
            float dl = rs2*Sv[jj] - bco2*G3f[jj] + C3f[jj];
            th[jj] = fminf(fmaxf(th[jj] + ssi*dl, LO[jj]), HI[jj]);
        }
        float* pa = outAng + ((size_t)(it+1)*B_TOT + s)*7;
#pragma unroll
        for (int jj = 0; jj < 7; jj++) pa[jj] = th[jj];
        __syncwarp();   // S reads done before next iter's x staging overwrites
    }
}

extern "C" void kernel_launch(void* const* d_in, const int* in_sizes, int n_in,
                              void* d_out, int out_size) {
    (void)in_sizes; (void)n_in; (void)out_size;
    cudaFuncSetAttribute(irm_kernel, cudaFuncAttributeMaxDynamicSharedMemorySize, SMEM_BYTES);
    irm_kernel<<<CTAS, THREADS, SMEM_BYTES>>>(
        (const float*)d_in[0], (const float*)d_in[1], (const float*)d_in[2],
        (const float*)d_in[4], (const float*)d_in[5], (const int*)d_in[6],
        (const float*)d_in[7],  (const float*)d_in[8],
        (const float*)d_in[9],  (const float*)d_in[10],
        (const float*)d_in[11], (const float*)d_in[12],
        (const float*)d_in[13], (const float*)d_in[14],
        (const float*)d_in[15], (const float*)d_in[16],
        (const float*)d_in[17],
        (float*)d_out);
}

// round 14
// speedup vs baseline: 1.2149x; 1.2149x over previous
#include <cuda_runtime.h>
#include <cuda_bf16.h>
#include <math.h>
#include <stdint.h>

#define B_TOT   262144
#define THREADS 256
#define CTAS    (B_TOT/THREADS)   // 1024

// ---- SMEM layout (bytes) ----
#define W2H_O   0        // W2 g1-folded hi: 128 rows x 272 B
#define W2L_O   34816    // W2 lo
#define W1H_O   69632    // W1 (+b1 row 28) hi: 32 rows x 272 B
#define W1L_O   78336    // W1 lo
#define W3G_O   87040    // float[128*8] g2-folded W3
#define G2C2_O  91136    // float2[128]
#define G3_O    92160    // 8 f
#define C3_O    92192    // 8 f
#define H1H_O   92224    // h1 hi: 256 rows x 272 B (x staging + H2 overlay here)
#define H1L_O   161856   // h1 lo
#define SMEM_BYTES 231488
#define H2_O    H1H_O    // overlay: 32 chunks x 4096 B (f32 [chunk][sample][4])

typedef unsigned long long u64;

static __device__ __forceinline__ u64 pk2(float lo, float hi) {
    u64 r; asm("mov.b64 %0,{%1,%2};" : "=l"(r) : "f"(lo), "f"(hi)); return r;
}
static __device__ __forceinline__ void upk2(u64 v, float &lo, float &hi) {
    asm("mov.b64 {%0,%1},%2;" : "=f"(lo), "=f"(hi) : "l"(v));
}
static __device__ __forceinline__ u64 ffma2(u64 a, u64 b, u64 c) {
    u64 d; asm("fma.rn.f32x2 %0,%1,%2,%3;" : "=l"(d) : "l"(a), "l"(b), "l"(c)); return d;
}
static __device__ __forceinline__ u64 fadd2(u64 a, u64 b) {
    u64 d; asm("add.rn.f32x2 %0,%1,%2;" : "=l"(d) : "l"(a), "l"(b)); return d;
}
// GELU(x) = x * Phi(x); Phi via Abramowitz-Stegun 7.1.26 erf (|err|<=1.5e-7),
// 0.5 folded into coefficients; MUFU rcp + exp.
static __device__ __forceinline__ float gelu_exact(float x) {
    float z = fabsf(x) * 0.70710678118654752f;
    float t = __fdividef(1.0f, fmaf(0.3275911f, z, 1.0f));
    float P = t*(0.127414796f + t*(-0.142248368f + t*(0.7107068705f + t*(-0.7265760135f + t*0.5307027145f))));
    float E = __expf(-z*z);
    float h = P * E;                         // 0.5*(1 - erf(z))
    float ph = copysignf(0.5f - h, x) + 0.5f; // Phi(x)
    return x * ph;
}
static __device__ __forceinline__ float red4(u64 a0, u64 a1) {
    float lo, hi; upk2(fadd2(a0, a1), lo, hi); return lo + hi;
}
static __device__ __forceinline__ uint32_t s2u(const void* p){
    uint32_t a; asm("{ .reg .u64 t; cvta.to.shared.u64 t, %1; cvt.u32.u64 %0, t; }":"=r"(a):"l"(p)); return a;
}
static __device__ __forceinline__ void ldsm4(uint32_t& r0,uint32_t& r1,uint32_t& r2,uint32_t& r3, uint32_t a){
    asm volatile("ldmatrix.sync.aligned.m8n8.x4.shared.b16 {%0,%1,%2,%3}, [%4];"
        : "=r"(r0),"=r"(r1),"=r"(r2),"=r"(r3) : "r"(a));
}
static __device__ __forceinline__ void ldsm4t(uint32_t& r0,uint32_t& r1,uint32_t& r2,uint32_t& r3, uint32_t a){
    asm volatile("ldmatrix.sync.aligned.m8n8.x4.trans.shared.b16 {%0,%1,%2,%3}, [%4];"
        : "=r"(r0),"=r"(r1),"=r"(r2),"=r"(r3) : "r"(a));
}
static __device__ __forceinline__ void mma16816(float* d, const uint32_t* a, uint32_t b0, uint32_t b1){
    asm volatile("mma.sync.aligned.m16n8k16.row.col.f32.bf16.bf16.f32 "
        "{%0,%1,%2,%3}, {%4,%5,%6,%7}, {%8,%9}, {%0,%1,%2,%3};"
        : "+f"(d[0]),"+f"(d[1]),"+f"(d[2]),"+f"(d[3])
        : "r"(a[0]),"r"(a[1]),"r"(a[2]),"r"(a[3]), "r"(b0),"r"(b1));
}

#define FKJ(F00,F01,F02,F10,F11,F12,F20,F21,F22,PX,PY,PZ,TH) do {              \
    float s_, c_; __sincosf((TH), &s_, &c_);                                   \
    tx += r00*(PX) + r01*(PY) + r02*(PZ);                                      \
    ty += r10*(PX) + r11*(PY) + r12*(PZ);                                      \
    tz += r20*(PX) + r21*(PY) + r22*(PZ);                                      \
    float A0 = r00*(F00) + r01*(F10) + r02*(F20);                              \
    float A1 = r10*(F00) + r11*(F10) + r12*(F20);                              \
    float A2 = r20*(F00) + r21*(F10) + r22*(F20);                              \
    float B0 = r00*(F01) + r01*(F11) + r02*(F21);                              \
    float B1 = r10*(F01) + r11*(F11) + r12*(F21);                              \
    float B2 = r20*(F01) + r21*(F11) + r22*(F21);                              \
    float C0 = r00*(F02) + r01*(F12) + r02*(F22);                              \
    float C1 = r10*(F02) + r11*(F12) + r12*(F22);                              \
    float C2v = r20*(F02) + r21*(F12) + r22*(F22);                             \
    r00 = c_*A0 + s_*B0;  r01 = c_*B0 - s_*A0;  r02 = C0;                      \
    r10 = c_*A1 + s_*B1;  r11 = c_*B1 - s_*A1;  r12 = C1;                      \
    r20 = c_*A2 + s_*B2;  r21 = c_*B2 - s_*A2;  r22 = C2v;                     \
} while (0)

static __device__ __forceinline__ void front_sample(
    int s, int it, const float* th, float vm,
    const float* __restrict__ tgt2d, const float* __restrict__ camK,
    const float* __restrict__ Rext,  const float* __restrict__ text,
    float* __restrict__ outAllKp, float* __restrict__ outKp,
    float* __restrict__ outTheta, u64* xp, int last)
{
    float kx[7], ky[7], kz[7];
    float r00=1.f,r01=0.f,r02=0.f, r10=0.f,r11=1.f,r12=0.f, r20=0.f,r21=0.f,r22=1.f;
    float tx=0.f, ty=0.f, tz=0.f;
    FKJ(1,0,0,  0,1,0,  0,0,1,   0.f,      0.f,     0.333f, th[0]);
    FKJ(1,0,0,  0,0,1,  0,-1,0,  0.f,      0.f,     0.f,    th[1]);
    kx[1]=tx; ky[1]=ty; kz[1]=tz;
    FKJ(1,0,0,  0,0,-1, 0,1,0,   0.f,     -0.316f,  0.f,    th[2]);
    kx[2]=tx; ky[2]=ty; kz[2]=tz;
    FKJ(1,0,0,  0,0,-1, 0,1,0,   0.0825f,  0.f,     0.f,    th[3]);
    kx[3]=tx; ky[3]=ty; kz[3]=tz;
    FKJ(1,0,0,  0,0,1,  0,-1,0, -0.0825f,  0.384f,  0.f,    th[4]);
    FKJ(1,0,0,  0,0,-1, 0,1,0,   0.f,      0.f,     0.f,    th[5]);
    kx[4]=tx; ky[4]=ty; kz[4]=tz;
    FKJ(1,0,0,  0,0,-1, 0,1,0,   0.088f,   0.f,     0.f,    th[6]);
    kx[5]=tx; ky[5]=ty; kz[5]=tz;
    kx[6]=tx + 0.107f*r02; ky[6]=ty + 0.107f*r12; kz[6]=tz + 0.107f*r22;
    kx[0]=0.f; ky[0]=0.f; kz[0]=0.f;
    {
        float* p = outAllKp + ((size_t)it * B_TOT + s) * 21;
#pragma unroll
        for (int k = 0; k < 7; k++) { p[3*k]=kx[k]; p[3*k+1]=ky[k]; p[3*k+2]=kz[k]; }
    }
    if (last) {
#pragma unroll
        for (int jj = 0; jj < 7; jj++) outTheta[(size_t)s*7 + jj] = th[jj];
        float* pkf = outKp + (size_t)s*21;
#pragma unroll
        for (int k = 0; k < 7; k++) { pkf[3*k]=kx[k]; pkf[3*k+1]=ky[k]; pkf[3*k+2]=kz[k]; }
        return;
    }
    float re[9], Kc[9], te[3];
#pragma unroll
    for (int i = 0; i < 9; i++) { re[i] = Rext[(size_t)s*9+i]; Kc[i] = camK[(size_t)s*9+i]; }
#pragma unroll
    for (int i = 0; i < 3; i++) te[i] = text[(size_t)s*3+i];
    float dmag[7];
#pragma unroll
    for (int k = 0; k < 7; k++) {
        float cxm = re[0]*kx[k] + re[1]*ky[k] + re[2]*kz[k] + te[0];
        float cym = re[3]*kx[k] + re[4]*ky[k] + re[5]*kz[k] + te[1];
        float czm = re[6]*kx[k] + re[7]*ky[k] + re[8]*kz[k] + te[2];
        float iz = 1.0f / fmaxf(czm, 1e-6f);
        float nx = cxm*iz, ny = cym*iz, nz = czm*iz;
        float u = Kc[0]*nx + Kc[1]*ny + Kc[2]*nz;
        float v = Kc[3]*nx + Kc[4]*ny + Kc[5]*nz;
        float du = (tgt2d[(size_t)s*14 + 2*k    ] - u) * vm;
        float dv = (tgt2d[(size_t)s*14 + 2*k + 1] - v) * vm;
        xp[k] = pk2(du, dv);
        dmag[k] = sqrtf(du*du + dv*dv);
    }
    xp[7]  = pk2(th[0], th[1]);   xp[8]  = pk2(th[2], th[3]);
    xp[9]  = pk2(th[4], th[5]);   xp[10] = pk2(th[6], dmag[0]);
    xp[11] = pk2(dmag[1], dmag[2]); xp[12] = pk2(dmag[3], dmag[4]);
    xp[13] = pk2(dmag[5], dmag[6]);
}

__global__ __launch_bounds__(THREADS,1)
void irm_kernel(const float* __restrict__ ang0,  const float* __restrict__ tgt2d,
                const float* __restrict__ camK,  const float* __restrict__ Rext,
                const float* __restrict__ text,  const int* __restrict__ vmask,
                const float* __restrict__ W1,    const float* __restrict__ b1,
                const float* __restrict__ g1,    const float* __restrict__ be1,
                const float* __restrict__ W2,    const float* __restrict__ b2,
                const float* __restrict__ g2,    const float* __restrict__ be2,
                const float* __restrict__ W3,    const float* __restrict__ b3,
                const float* __restrict__ slog,  float* __restrict__ out)
{
    extern __shared__ float smf[];
    char* const smc = (char*)smf;
    const uint32_t sbase = s2u(smc);
    const int tid = threadIdx.x;
    const int wid = tid >> 5, lane = tid & 31;

    // ================= weight preprocessing =================
    for (int idx = tid; idx < 16384; idx += THREADS) {
        int k = idx >> 7, j = idx & 127;
        float v = g1[k] * W2[k*128 + j];
        __nv_bfloat16 h = __float2bfloat16(v);
        __nv_bfloat16 l = __float2bfloat16(v - __bfloat162float(h));
        *(__nv_bfloat16*)(smc + W2H_O + k*272 + j*2) = h;
        *(__nv_bfloat16*)(smc + W2L_O + k*272 + j*2) = l;
    }
    for (int idx = tid; idx < 4096; idx += THREADS) {
        int k = idx >> 7, j = idx & 127;
        float v = (k < 28) ? W1[k*128 + j] : ((k == 28) ? b1[j] : 0.f);
        __nv_bfloat16 h = __float2bfloat16(v);
        __nv_bfloat16 l = __float2bfloat16(v - __bfloat162float(h));
        *(__nv_bfloat16*)(smc + W1H_O + k*272 + j*2) = h;
        *(__nv_bfloat16*)(smc + W1L_O + k*272 + j*2) = l;
    }
    if (tid < 128) {
        float ga = 0.f, ca = 0.f;
        for (int k = 0; k < 128; k++) { float w = W2[k*128 + tid]; ga += g1[k]*w; ca += be1[k]*w; }
        ((float2*)(smc + G2C2_O))[tid] = make_float2(ga, ca + b2[tid]);
    }
    for (int idx = tid; idx < 512; idx += THREADS) {
        int k = idx & 127, p = idx >> 7;
        float gk = g2[k];
        int j0 = 2*p, j1 = 2*p + 1;
        smf[W3G_O/4 + k*8 + p*2]     = gk * W3[k*7 + j0];
        smf[W3G_O/4 + k*8 + p*2 + 1] = (j1 < 7) ? gk * W3[k*7 + j1] : 0.0f;
    }
    if (tid < 8) {
        float ga = 0.f, ca = 0.f;
        if (tid < 7) {
            for (int k = 0; k < 128; k++) { float w = W3[k*7 + tid]; ga += g2[k]*w; ca += be2[k]*w; }
            ca += b3[tid];
        }
        smf[G3_O/4 + tid] = ga;  smf[C3_O/4 + tid] = ca;
    }
    __syncthreads();

    // ================= per-thread sample =================
    const int s = blockIdx.x * THREADS + tid;
    float th[7];
#pragma unroll
    for (int j = 0; j < 7; j++) th[j] = ang0[s*7 + j];
    const float vm = (vmask[s] != 0) ? 1.0f : 0.0f;

    float* const outTheta = out;
    float* const outKp    = out + (size_t)B_TOT*7;
    float* const outAng   = out + (size_t)B_TOT*28;
    float* const outAllKp = out + (size_t)B_TOT*56;
#pragma unroll
    for (int j = 0; j < 7; j++) outAng[(size_t)s*7 + j] = th[j];

    // fragment geometry
    const int lidx = lane >> 3, lr = lane & 7;
    const int dm = lane >> 2, q = lane & 3;
    const uint32_t frag272 = (uint32_t)(((lidx & 1)*8 + lr)*272 + (lidx >> 1)*16);
    const uint32_t frag80  = (uint32_t)(((lidx & 1)*8 + lr)*80  + (lidx >> 1)*16);
    const uint32_t wslot   = (uint32_t)wid * 8704u;
    const uint32_t xAddrH  = sbase + H1H_O + wslot + frag80;   // x hi (stripe +1280, ks +32)
    const uint32_t aAddr0  = sbase + H1H_O + wslot + frag272;  // h1 A for MMA2
    const uint32_t aAddr1  = aAddr0 + 16u*272u;
    const uint32_t w1Addr  = sbase + W1H_O + frag272;
    const uint32_t bAddr   = sbase + W2H_O + frag272;
    const int dj  = 2*q;

    for (int it = 0; it < 4; ++it) {
        u64 xp[14];
        const int last = (it == 3);
        front_sample(s, it, th, vm, tgt2d, camK, Rext, text, outAllKp, outKp, outTheta, xp, last);
        if (last) break;

        // ---------------- stage x (bf16 hi/lo) into per-warp slot ----------------
        {
            uint32_t xh[16], xl[16];
#pragma unroll
            for (int c = 0; c < 14; c++) {
                float v0, v1; upk2(xp[c], v0, v1);
                __nv_bfloat162 H = __floats2bfloat162_rn(v0, v1);
                __nv_bfloat162 L = __floats2bfloat162_rn(v0 - __low2float(H), v1 - __high2float(H));
                xh[c] = *(uint32_t*)&H;  xl[c] = *(uint32_t*)&L;
            }
            __nv_bfloat162 Hb = __floats2bfloat162_rn(1.0f, 0.0f);
            xh[14] = *(uint32_t*)&Hb;  xl[14] = 0u;  xh[15] = 0u;  xl[15] = 0u;
            char* px = smc + H1H_O + wslot + lane*80;
            *(uint4*)(px)      = make_uint4(xh[0],xh[1],xh[2],xh[3]);
            *(uint4*)(px + 16) = make_uint4(xh[4],xh[5],xh[6],xh[7]);
            *(uint4*)(px + 32) = make_uint4(xh[8],xh[9],xh[10],xh[11]);
            *(uint4*)(px + 48) = make_uint4(xh[12],xh[13],xh[14],xh[15]);
            char* pl = px + (H1L_O - H1H_O);
            *(uint4*)(pl)      = make_uint4(xl[0],xl[1],xl[2],xl[3]);
            *(uint4*)(pl + 16) = make_uint4(xl[4],xl[5],xl[6],xl[7]);
            *(uint4*)(pl + 32) = make_uint4(xl[8],xl[9],xl[10],xl[11]);
            *(uint4*)(pl + 48) = make_uint4(xl[12],xl[13],xl[14],xl[15]);
        }
        __syncwarp();

        // ---------------- MMA1: h1pre = x @ W1 (+bias row) ----------------
        uint32_t a1h[2][2][4], a1l[2][2][4];
#pragma unroll
        for (int st = 0; st < 2; st++)
#pragma unroll
            for (int ks = 0; ks < 2; ks++) {
                uint32_t base = xAddrH + st*1280 + ks*32;
                ldsm4(a1h[st][ks][0],a1h[st][ks][1],a1h[st][ks][2],a1h[st][ks][3], base);
                ldsm4(a1l[st][ks][0],a1l[st][ks][1],a1l[st][ks][2],a1l[st][ks][3], base + (H1L_O - H1H_O));
            }

        u64 sP[2][2] = {{0,0},{0,0}}, qP[2][2] = {{0,0},{0,0}};
        float rs1v[2][2], bc1v[2][2];

        for (int nh = 0; nh < 2; nh++) {
            float acc1[2][8][4];
#pragma unroll
            for (int st2 = 0; st2 < 2; st2++)
#pragma unroll
                for (int t = 0; t < 8; t++)
#pragma unroll
                    for (int e = 0; e < 4; e++) acc1[st2][t][e] = 0.f;
#pragma unroll
            for (int ks = 0; ks < 2; ks++)
#pragma unroll
                for (int gl = 0; gl < 4; gl++) {
                    uint32_t ba = w1Addr + (uint32_t)ks*4352u + (uint32_t)(nh*4+gl)*32u;
                    uint32_t bh0,bh1,bh2,bh3, bl0,bl1,bl2,bl3;
                    ldsm4t(bh0,bh1,bh2,bh3, ba);
                    ldsm4t(bl0,bl1,bl2,bl3, ba + (W1L_O - W1H_O));
#pragma unroll
                    for (int st2 = 0; st2 < 2; st2++) {
                        mma16816(acc1[st2][2*gl],   a1h[st2][ks], bh0, bh1);
                        mma16816(acc1[st2][2*gl],   a1l[st2][ks], bh0, bh1);
                        mma16816(acc1[st2][2*gl],   a1h[st2][ks], bl0, bl1);
                        mma16816(acc1[st2][2*gl+1], a1h[st2][ks], bh2, bh3);
                        mma16816(acc1[st2][2*gl+1], a1l[st2][ks], bh2, bh3);
                        mma16816(acc1[st2][2*gl+1], a1h[st2][ks], bl2, bl3);
                    }
                }
            // epi1 on fragments: GELU, LN1 stats, h1 -> SMEM (bf16 hi/lo)
#pragma unroll
            for (int st2 = 0; st2 < 2; st2++)
#pragma unroll
                for (int t = 0; t < 8; t++) {
                    float v0 = gelu_exact(acc1[st2][t][0]);
                    float v1 = gelu_exact(acc1[st2][t][1]);
                    float v2 = gelu_exact(acc1[st2][t][2]);
                    float v3 = gelu_exact(acc1[st2][t][3]);
                    u64 p01 = pk2(v0,v1), p23 = pk2(v2,v3);
                    sP[st2][0] = fadd2(sP[st2][0], p01);
                    qP[st2][0] = ffma2(p01, p01, qP[st2][0]);
                    sP[st2][1] = fadd2(sP[st2][1], p23);
                    qP[st2][1] = ffma2(p23, p23, qP[st2][1]);
                    __nv_bfloat162 H0 = __floats2bfloat162_rn(v0, v1);
                    __nv_bfloat162 L0 = __floats2bfloat162_rn(v0 - __low2float(H0), v1 - __high2float(H0));
                    __nv_bfloat162 H1 = __floats2bfloat162_rn(v2, v3);
                    __nv_bfloat162 L1 = __floats2bfloat162_rn(v2 - __low2float(H1), v3 - __high2float(H1));
                    uint32_t colb = (uint32_t)(((nh*8 + t)*8 + dj)*2);
                    char* r0p = smc + H1H_O + wslot + (uint32_t)(st2*16 + dm)*272u + colb;
                    char* r1p = smc + H1H_O + wslot + (uint32_t)(st2*16 + dm + 8)*272u + colb;
                    *(uint32_t*)r0p = *(uint32_t*)&H0;
                    *(uint32_t*)r1p = *(uint32_t*)&H1;
                    *(uint32_t*)(r0p + (H1L_O - H1H_O)) = *(uint32_t*)&L0;
                    *(uint32_t*)(r1p + (H1L_O - H1H_O)) = *(uint32_t*)&L1;
                }
        }
        __syncwarp();

        // LN1 stats finalize (4-lane row groups) + broadcast to sample threads
#pragma unroll
        for (int st2 = 0; st2 < 2; st2++)
#pragma unroll
            for (int h = 0; h < 2; h++) {
                float a, b; upk2(sP[st2][h], a, b); float sum = a + b;
                upk2(qP[st2][h], a, b); float sq = a + b;
                sum += __shfl_xor_sync(0xFFFFFFFFu, sum, 1);
                sum += __shfl_xor_sync(0xFFFFFFFFu, sum, 2);
                sq  += __shfl_xor_sync(0xFFFFFFFFu, sq, 1);
                sq  += __shfl_xor_sync(0xFFFFFFFFu, sq, 2);
                float mu = sum * (1.0f/128.0f);
                float rs = rsqrtf(sq*(1.0f/128.0f) - mu*mu + 1e-5f);
                rs1v[st2][h] = rs;  bc1v[st2][h] = rs*mu;
            }
        float rs1 = 0.f, bco1 = 0.f;
        {
            const int st_s = lane >> 4, h_s = (lane >> 3) & 1, src = (lane & 7)*4;
#pragma unroll
            for (int st2 = 0; st2 < 2; st2++)
#pragma unroll
                for (int h = 0; h < 2; h++) {
                    float tr = __shfl_sync(0xFFFFFFFFu, rs1v[st2][h], src);
                    float tb = __shfl_sync(0xFFFFFFFFu, bc1v[st2][h], src);
                    if (st2 == st_s && h == h_s) { rs1 = tr; bco1 = tb; }
                }
        }

        // ---------------- layer 2 via mma.sync ----------------
        float acc[2][16][4];
#pragma unroll
        for (int st2 = 0; st2 < 2; st2++)
#pragma unroll
            for (int t = 0; t < 16; t++)
#pragma unroll
                for (int e = 0; e < 4; e++) acc[st2][t][e] = 0.f;

        for (int ks = 0; ks < 8; ks++) {
            uint32_t ah[2][4], al[2][4];
            ldsm4(ah[0][0],ah[0][1],ah[0][2],ah[0][3], aAddr0 + ks*32);
            ldsm4(al[0][0],al[0][1],al[0][2],al[0][3], aAddr0 + ks*32 + (H1L_O - H1H_O));
            ldsm4(ah[1][0],ah[1][1],ah[1][2],ah[1][3], aAddr1 + ks*32);
            ldsm4(al[1][0],al[1][1],al[1][2],al[1][3], aAddr1 + ks*32 + (H1L_O - H1H_O));
#pragma unroll
            for (int jt2 = 0; jt2 < 8; jt2++) {
                uint32_t bh0,bh1,bh2,bh3, bl0,bl1,bl2,bl3;
                uint32_t ba = bAddr + (uint32_t)ks*16u*272u + (uint32_t)jt2*32u;
                ldsm4t(bh0,bh1,bh2,bh3, ba);
                ldsm4t(bl0,bl1,bl2,bl3, ba + (W2L_O - W2H_O));
#pragma unroll
                for (int st2 = 0; st2 < 2; st2++) {
                    mma16816(acc[st2][2*jt2],   ah[st2], bh0, bh1);
                    mma16816(acc[st2][2*jt2],   al[st2], bh0, bh1);
                    mma16816(acc[st2][2*jt2],   ah[st2], bl0, bl1);
                    mma16816(acc[st2][2*jt2+1], ah[st2], bh2, bh3);
                    mma16816(acc[st2][2*jt2+1], al[st2], bh2, bh3);
                    mma16816(acc[st2][2*jt2+1], ah[st2], bl2, bl3);
                }
            }
        }
        __syncthreads();   // all warps done with h1/x before H2 overlays region

        // write H2 [chunk(j/4)][sample][4 f32]
#pragma unroll
        for (int st2 = 0; st2 < 2; st2++) {
            const int m0 = wid*32 + st2*16 + dm;
#pragma unroll
            for (int t = 0; t < 16; t++) {
                const int j0 = t*8 + dj;
                const uint32_t base = H2_O + (uint32_t)(j0 >> 2)*4096u + ((j0 & 3) << 2);
                *(float2*)(smc + base + m0*16)       = make_float2(acc[st2][t][0], acc[st2][t][1]);
                *(float2*)(smc + base + (m0+8)*16)   = make_float2(acc[st2][t][2], acc[st2][t][3]);
            }
        }
        __syncwarp();

        // ---------------- readback: LN1-fold -> GELU -> LN2 stats + layer 3 ----------------
        float sum2 = 0.f, sq2 = 0.f;
        u64 S0=0,S1=0,S2=0,S3=0;
        const float2* const G2C2 = (const float2*)(smc + G2C2_O);
        for (int c = 0; c < 32; c++) {
            float4 t4 = *(const float4*)(smc + H2_O + c*4096 + tid*16);
            float tv[4] = {t4.x, t4.y, t4.z, t4.w};
#pragma unroll
            for (int e = 0; e < 4; e++) {
                const int row = 4*c + e;
                float2 gc = G2C2[row];
                float v = gelu_exact(rs1*tv[e] - bco1*gc.x + gc.y);
                sum2 += v; sq2 += v*v;
                const ulonglong2* w3r = (const ulonglong2*)(smf + W3G_O/4 + row*8);
                ulonglong2 wa3 = w3r[0], wb3 = w3r[1];
                u64 v2 = pk2(v,v);
                S0 = ffma2(v2, wa3.x, S0);  S1 = ffma2(v2, wa3.y, S1);
                S2 = ffma2(v2, wb3.x, S2);  S3 = ffma2(v2, wb3.y, S3);
            }
        }
        float mu2 = sum2*(1.0f/128.0f);
        float rs2 = rsqrtf(sq2*(1.0f/128.0f) - mu2*mu2 + 1e-5f);
        float bco2 = rs2*mu2;
        float sv[8];
        upk2(S0, sv[0], sv[1]); upk2(S1, sv[2], sv[3]);
        upk2(S2, sv[4], sv[5]); upk2(S3, sv[6], sv[7]);

        const float ssi = 1.0f/(1.0f + expf(-slog[it]));
        const float LO[7] = {-2.8973f,-1.7628f,-2.8973f,-3.0718f,-2.8973f,-0.0175f,-2.8973f};
        const float HI[7] = { 2.8973f, 1.7628f, 2.8973f,-0.0698f, 2.8973f, 3.7525f, 2.8973f};
#pragma unroll
        for (int jj = 0; jj < 7; jj++) {
            float dl = rs2*sv[jj] - bco2*smf[G3_O/4 + jj] + smf[C3_O/4 + jj];
            th[jj] = fminf(fmaxf(th[jj] + ssi*dl, LO[jj]), HI[jj]);
        }
        float* pa = outAng + ((size_t)(it+1)*B_TOT + s)*7;
#pragma unroll
        for (int jj = 0; jj < 7; jj++) pa[jj] = th[jj];

        __syncthreads();   // H2 reads done before next iter's x/h1 writes
    }
}

extern "C" void kernel_launch(void* const* d_in, const int* in_sizes, int n_in,
                              void* d_out, int out_size) {
    (void)in_sizes; (void)n_in; (void)out_size;
    cudaFuncSetAttribute(irm_kernel, cudaFuncAttributeMaxDynamicSharedMemorySize, SMEM_BYTES);
    irm_kernel<<<CTAS, THREADS, SMEM_BYTES>>>(
        (const float*)d_in[0], (const float*)d_in[1], (const float*)d_in[2],
        (const float*)d_in[4], (const float*)d_in[5], (const int*)d_in[6],
        (const float*)d_in[7],  (const float*)d_in[8],
        (const float*)d_in[9],  (const float*)d_in[10],
        (const float*)d_in[11], (const float*)d_in[12],
        (const float*)d_in[13], (const float*)d_in[14],
        (const float*)d_in[15], (const float*)d_in[16],
        (const float*)d_in[17],
        (float*)d_out);
}

// round 15
// speedup vs baseline: 1.3333x; 1.0975x over previous
#include <cuda_runtime.h>
#include <cuda_bf16.h>
#include <math.h>
#include <stdint.h>

#define B_TOT   262144
#define THREADS 256
#define CTAS    (B_TOT/THREADS)   // 1024

// ---- SMEM layout (bytes) ----
#define W2H_O   0        // W2 g1-folded hi: 128 rows x 272 B
#define W2L_O   34816    // W2 lo
#define W1H_O   69632    // W1 (+b1 row 28) hi: 32 rows x 272 B
#define W1L_O   78336    // W1 lo
#define W3G_O   87040    // float[128*8] g2-folded W3
#define G2C2_O  91136    // float2[128]
#define G3_O    92160    // 8 f
#define C3_O    92192    // 8 f
#define H1H_O   92224    // per-warp slots (8704 B): x-hi staging + H2 chunks 0..15
#define H1L_O   161856   // per-warp slots: x-lo staging + H2 chunks 16..31
#define SMEM_BYTES 231488

typedef unsigned long long u64;

static __device__ __forceinline__ u64 pk2(float lo, float hi) {
    u64 r; asm("mov.b64 %0,{%1,%2};" : "=l"(r) : "f"(lo), "f"(hi)); return r;
}
static __device__ __forceinline__ void upk2(u64 v, float &lo, float &hi) {
    asm("mov.b64 {%0,%1},%2;" : "=f"(lo), "=f"(hi) : "l"(v));
}
static __device__ __forceinline__ u64 ffma2(u64 a, u64 b, u64 c) {
    u64 d; asm("fma.rn.f32x2 %0,%1,%2,%3;" : "=l"(d) : "l"(a), "l"(b), "l"(c)); return d;
}
static __device__ __forceinline__ u64 fadd2(u64 a, u64 b) {
    u64 d; asm("add.rn.f32x2 %0,%1,%2;" : "=l"(d) : "l"(a), "l"(b)); return d;
}
// GELU(x) = x * Phi(x); A&S 7.1.26 erf (|err|<=1.5e-7), MUFU rcp + exp.
static __device__ __forceinline__ float gelu_exact(float x) {
    float z = fabsf(x) * 0.70710678118654752f;
    float t = __fdividef(1.0f, fmaf(0.3275911f, z, 1.0f));
    float P = t*(0.127414796f + t*(-0.142248368f + t*(0.7107068705f + t*(-0.7265760135f + t*0.5307027145f))));
    float E = __expf(-z*z);
    float h = P * E;
    float ph = copysignf(0.5f - h, x) + 0.5f;
    return x * ph;
}
static __device__ __forceinline__ uint32_t s2u(const void* p){
    uint32_t a; asm("{ .reg .u64 t; cvta.to.shared.u64 t, %1; cvt.u32.u64 %0, t; }":"=r"(a):"l"(p)); return a;
}
static __device__ __forceinline__ void ldsm4(uint32_t& r0,uint32_t& r1,uint32_t& r2,uint32_t& r3, uint32_t a){
    asm volatile("ldmatrix.sync.aligned.m8n8.x4.shared.b16 {%0,%1,%2,%3}, [%4];"
        : "=r"(r0),"=r"(r1),"=r"(r2),"=r"(r3) : "r"(a));
}
static __device__ __forceinline__ void ldsm4t(uint32_t& r0,uint32_t& r1,uint32_t& r2,uint32_t& r3, uint32_t a){
    asm volatile("ldmatrix.sync.aligned.m8n8.x4.trans.shared.b16 {%0,%1,%2,%3}, [%4];"
        : "=r"(r0),"=r"(r1),"=r"(r2),"=r"(r3) : "r"(a));
}
static __device__ __forceinline__ void mma16816(float* d, const uint32_t* a, uint32_t b0, uint32_t b1){
    asm volatile("mma.sync.aligned.m16n8k16.row.col.f32.bf16.bf16.f32 "
        "{%0,%1,%2,%3}, {%4,%5,%6,%7}, {%8,%9}, {%0,%1,%2,%3};"
        : "+f"(d[0]),"+f"(d[1]),"+f"(d[2]),"+f"(d[3])
        : "r"(a[0]),"r"(a[1]),"r"(a[2]),"r"(a[3]), "r"(b0),"r"(b1));
}

#define FKJ(F00,F01,F02,F10,F11,F12,F20,F21,F22,PX,PY,PZ,TH) do {              \
    float s_, c_; __sincosf((TH), &s_, &c_);                                   \
    tx += r00*(PX) + r01*(PY) + r02*(PZ);                                      \
    ty += r10*(PX) + r11*(PY) + r12*(PZ);                                      \
    tz += r20*(PX) + r21*(PY) + r22*(PZ);                                      \
    float A0 = r00*(F00) + r01*(F10) + r02*(F20);                              \
    float A1 = r10*(F00) + r11*(F10) + r12*(F20);                              \
    float A2 = r20*(F00) + r21*(F10) + r22*(F20);                              \
    float B0 = r00*(F01) + r01*(F11) + r02*(F21);                              \
    float B1 = r10*(F01) + r11*(F11) + r12*(F21);                              \
    float B2 = r20*(F01) + r21*(F11) + r22*(F21);                              \
    float C0 = r00*(F02) + r01*(F12) + r02*(F22);                              \
    float C1 = r10*(F02) + r11*(F12) + r12*(F22);                              \
    float C2v = r20*(F02) + r21*(F12) + r22*(F22);                             \
    r00 = c_*A0 + s_*B0;  r01 = c_*B0 - s_*A0;  r02 = C0;                      \
    r10 = c_*A1 + s_*B1;  r11 = c_*B1 - s_*A1;  r12 = C1;                      \
    r20 = c_*A2 + s_*B2;  r21 = c_*B2 - s_*A2;  r22 = C2v;                     \
} while (0)

static __device__ __forceinline__ void front_sample(
    int s, int it, const float* th, float vm,
    const float* __restrict__ tgt2d, const float* __restrict__ camK,
    const float* __restrict__ Rext,  const float* __restrict__ text,
    float* __restrict__ outAllKp, float* __restrict__ outKp,
    float* __restrict__ outTheta, u64* xp, int last)
{
    float kx[7], ky[7], kz[7];
    float r00=1.f,r01=0.f,r02=0.f, r10=0.f,r11=1.f,r12=0.f, r20=0.f,r21=0.f,r22=1.f;
    float tx=0.f, ty=0.f, tz=0.f;
    FKJ(1,0,0,  0,1,0,  0,0,1,   0.f,      0.f,     0.333f, th[0]);
    FKJ(1,0,0,  0,0,1,  0,-1,0,  0.f,      0.f,     0.f,    th[1]);
    kx[1]=tx; ky[1]=ty; kz[1]=tz;
    FKJ(1,0,0,  0,0,-1, 0,1,0,   0.f,     -0.316f,  0.f,    th[2]);
    kx[2]=tx; ky[2]=ty; kz[2]=tz;
    FKJ(1,0,0,  0,0,-1, 0,1,0,   0.0825f,  0.f,     0.f,    th[3]);
    kx[3]=tx; ky[3]=ty; kz[3]=tz;
    FKJ(1,0,0,  0,0,1,  0,-1,0, -0.0825f,  0.384f,  0.f,    th[4]);
    FKJ(1,0,0,  0,0,-1, 0,1,0,   0.f,      0.f,     0.f,    th[5]);
    kx[4]=tx; ky[4]=ty; kz[4]=tz;
    FKJ(1,0,0,  0,0,-1, 0,1,0,   0.088f,   0.f,     0.f,    th[6]);
    kx[5]=tx; ky[5]=ty; kz[5]=tz;
    kx[6]=tx + 0.107f*r02; ky[6]=ty + 0.107f*r12; kz[6]=tz + 0.107f*r22;
    kx[0]=0.f; ky[0]=0.f; kz[0]=0.f;
    {
        float* p = outAllKp + ((size_t)it * B_TOT + s) * 21;
#pragma unroll
        for (int k = 0; k < 7; k++) { p[3*k]=kx[k]; p[3*k+1]=ky[k]; p[3*k+2]=kz[k]; }
    }
    if (last) {
#pragma unroll
        for (int jj = 0; jj < 7; jj++) outTheta[(size_t)s*7 + jj] = th[jj];
        float* pkf = outKp + (size_t)s*21;
#pragma unroll
        for (int k = 0; k < 7; k++) { pkf[3*k]=kx[k]; pkf[3*k+1]=ky[k]; pkf[3*k+2]=kz[k]; }
        return;
    }
    float re[9], Kc[9], te[3];
#pragma unroll
    for (int i = 0; i < 9; i++) { re[i] = Rext[(size_t)s*9+i]; Kc[i] = camK[(size_t)s*9+i]; }
#pragma unroll
    for (int i = 0; i < 3; i++) te[i] = text[(size_t)s*3+i];
    float dmag[7];
#pragma unroll
    for (int k = 0; k < 7; k++) {
        float cxm = re[0]*kx[k] + re[1]*ky[k] + re[2]*kz[k] + te[0];
        float cym = re[3]*kx[k] + re[4]*ky[k] + re[5]*kz[k] + te[1];
        float czm = re[6]*kx[k] + re[7]*ky[k] + re[8]*kz[k] + te[2];
        float iz = 1.0f / fmaxf(czm, 1e-6f);
        float nx = cxm*iz, ny = cym*iz, nz = czm*iz;
        float u = Kc[0]*nx + Kc[1]*ny + Kc[2]*nz;
        float v = Kc[3]*nx + Kc[4]*ny + Kc[5]*nz;
        float du = (tgt2d[(size_t)s*14 + 2*k    ] - u) * vm;
        float dv = (tgt2d[(size_t)s*14 + 2*k + 1] - v) * vm;
        xp[k] = pk2(du, dv);
        dmag[k] = sqrtf(du*du + dv*dv);
    }
    xp[7]  = pk2(th[0], th[1]);   xp[8]  = pk2(th[2], th[3]);
    xp[9]  = pk2(th[4], th[5]);   xp[10] = pk2(th[6], dmag[0]);
    xp[11] = pk2(dmag[1], dmag[2]); xp[12] = pk2(dmag[3], dmag[4]);
    xp[13] = pk2(dmag[5], dmag[6]);
}

__global__ __launch_bounds__(THREADS,1)
void irm_kernel(const float* __restrict__ ang0,  const float* __restrict__ tgt2d,
                const float* __restrict__ camK,  const float* __restrict__ Rext,
                const float* __restrict__ text,  const int* __restrict__ vmask,
                const float* __restrict__ W1,    const float* __restrict__ b1,
                const float* __restrict__ g1,    const float* __restrict__ be1,
                const float* __restrict__ W2,    const float* __restrict__ b2,
                const float* __restrict__ g2,    const float* __restrict__ be2,
                const float* __restrict__ W3,    const float* __restrict__ b3,
                const float* __restrict__ slog,  float* __restrict__ out)
{
    extern __shared__ float smf[];
    char* const smc = (char*)smf;
    const uint32_t sbase = s2u(smc);
    const int tid = threadIdx.x;
    const int wid = tid >> 5, lane = tid & 31;

    // ================= weight preprocessing =================
    for (int idx = tid; idx < 16384; idx += THREADS) {
        int k = idx >> 7, j = idx & 127;
        float v = g1[k] * W2[k*128 + j];
        __nv_bfloat16 h = __float2bfloat16(v);
        __nv_bfloat16 l = __float2bfloat16(v - __bfloat162float(h));
        *(__nv_bfloat16*)(smc + W2H_O + k*272 + j*2) = h;
        *(__nv_bfloat16*)(smc + W2L_O + k*272 + j*2) = l;
    }
    for (int idx = tid; idx < 4096; idx += THREADS) {
        int k = idx >> 7, j = idx & 127;
        float v = (k < 28) ? W1[k*128 + j] : ((k == 28) ? b1[j] : 0.f);
        __nv_bfloat16 h = __float2bfloat16(v);
        __nv_bfloat16 l = __float2bfloat16(v - __bfloat162float(h));
        *(__nv_bfloat16*)(smc + W1H_O + k*272 + j*2) = h;
        *(__nv_bfloat16*)(smc + W1L_O + k*272 + j*2) = l;
    }
    if (tid < 128) {
        float ga = 0.f, ca = 0.f;
        for (int k = 0; k < 128; k++) { float w = W2[k*128 + tid]; ga += g1[k]*w; ca += be1[k]*w; }
        ((float2*)(smc + G2C2_O))[tid] = make_float2(ga, ca + b2[tid]);
    }
    for (int idx = tid; idx < 512; idx += THREADS) {
        int k = idx & 127, p = idx >> 7;
        float gk = g2[k];
        int j0 = 2*p, j1 = 2*p + 1;
        smf[W3G_O/4 + k*8 + p*2]     = gk * W3[k*7 + j0];
        smf[W3G_O/4 + k*8 + p*2 + 1] = (j1 < 7) ? gk * W3[k*7 + j1] : 0.0f;
    }
    if (tid < 8) {
        float ga = 0.f, ca = 0.f;
        if (tid < 7) {
            for (int k = 0; k < 128; k++) { float w = W3[k*7 + tid]; ga += g2[k]*w; ca += be2[k]*w; }
            ca += b3[tid];
        }
        smf[G3_O/4 + tid] = ga;  smf[C3_O/4 + tid] = ca;
    }
    __syncthreads();

    // ================= per-thread sample =================
    const int s = blockIdx.x * THREADS + tid;
    float th[7];
#pragma unroll
    for (int j = 0; j < 7; j++) th[j] = ang0[s*7 + j];
    const float vm = (vmask[s] != 0) ? 1.0f : 0.0f;

    float* const outTheta = out;
    float* const outKp    = out + (size_t)B_TOT*7;
    float* const outAng   = out + (size_t)B_TOT*28;
    float* const outAllKp = out + (size_t)B_TOT*56;
#pragma unroll
    for (int j = 0; j < 7; j++) outAng[(size_t)s*7 + j] = th[j];

    // fragment geometry
    const int lidx = lane >> 3, lr = lane & 7;
    const int dm = lane >> 2, q = lane & 3;
    const uint32_t frag272 = (uint32_t)(((lidx & 1)*8 + lr)*272 + (lidx >> 1)*16);
    const uint32_t frag80  = (uint32_t)(((lidx & 1)*8 + lr)*80  + (lidx >> 1)*16);
    const uint32_t wslot   = (uint32_t)wid * 8704u;
    const uint32_t xAddrH  = sbase + H1H_O + wslot + frag80;   // x hi (stripe +1280, ks +32)
    const uint32_t w1Addr  = sbase + W1H_O + frag272;
    const uint32_t bAddr   = sbase + W2H_O + frag272;
    const int dj  = 2*q;
    // per-warp H2 chunk bases
    char* const h2A = smc + H1H_O + wslot;   // chunks 0..15 (512 B each)
    char* const h2B = smc + H1L_O + wslot;   // chunks 16..31

    for (int it = 0; it < 4; ++it) {
        u64 xp[14];
        const int last = (it == 3);
        front_sample(s, it, th, vm, tgt2d, camK, Rext, text, outAllKp, outKp, outTheta, xp, last);
        if (last) break;

        // ---------------- stage x (bf16 hi/lo) into per-warp slot ----------------
        {
            uint32_t xh[16], xl[16];
#pragma unroll
            for (int c = 0; c < 14; c++) {
                float v0, v1; upk2(xp[c], v0, v1);
                __nv_bfloat162 H = __floats2bfloat162_rn(v0, v1);
                __nv_bfloat162 L = __floats2bfloat162_rn(v0 - __low2float(H), v1 - __high2float(H));
                xh[c] = *(uint32_t*)&H;  xl[c] = *(uint32_t*)&L;
            }
            __nv_bfloat162 Hb = __floats2bfloat162_rn(1.0f, 0.0f);
            xh[14] = *(uint32_t*)&Hb;  xl[14] = 0u;  xh[15] = 0u;  xl[15] = 0u;
            char* px = smc + H1H_O + wslot + lane*80;
            *(uint4*)(px)      = make_uint4(xh[0],xh[1],xh[2],xh[3]);
            *(uint4*)(px + 16) = make_uint4(xh[4],xh[5],xh[6],xh[7]);
            *(uint4*)(px + 32) = make_uint4(xh[8],xh[9],xh[10],xh[11]);
            *(uint4*)(px + 48) = make_uint4(xh[12],xh[13],xh[14],xh[15]);
            char* pl = px + (H1L_O - H1H_O);
            *(uint4*)(pl)      = make_uint4(xl[0],xl[1],xl[2],xl[3]);
            *(uint4*)(pl + 16) = make_uint4(xl[4],xl[5],xl[6],xl[7]);
            *(uint4*)(pl + 32) = make_uint4(xl[8],xl[9],xl[10],xl[11]);
            *(uint4*)(pl + 48) = make_uint4(xl[12],xl[13],xl[14],xl[15]);
        }
        __syncwarp();

        // ---------------- A fragments of x ----------------
        uint32_t a1h[2][2][4], a1l[2][2][4];
#pragma unroll
        for (int st = 0; st < 2; st++)
#pragma unroll
            for (int ks = 0; ks < 2; ks++) {
                uint32_t base = xAddrH + st*1280 + ks*32;
                ldsm4(a1h[st][ks][0],a1h[st][ks][1],a1h[st][ks][2],a1h[st][ks][3], base);
                ldsm4(a1l[st][ks][0],a1l[st][ks][1],a1l[st][ks][2],a1l[st][ks][3], base + (H1L_O - H1H_O));
            }

        // ---------------- fused MMA1 -> GELU -> MMA2 (h1 stays in registers) ----------------
        float acc[2][16][4];
#pragma unroll
        for (int st2 = 0; st2 < 2; st2++)
#pragma unroll
            for (int t = 0; t < 16; t++)
#pragma unroll
                for (int e = 0; e < 4; e++) acc[st2][t][e] = 0.f;

        u64 sP[2][2] = {{0,0},{0,0}}, qP[2][2] = {{0,0},{0,0}};
        float rs1v[2][2], bc1v[2][2];

        for (int nh = 0; nh < 2; nh++) {
            float acc1[2][8][4];
#pragma unroll
            for (int st2 = 0; st2 < 2; st2++)
#pragma unroll
                for (int t = 0; t < 8; t++)
#pragma unroll
                    for (int e = 0; e < 4; e++) acc1[st2][t][e] = 0.f;
#pragma unroll
            for (int ks = 0; ks < 2; ks++)
#pragma unroll
                for (int gl = 0; gl < 4; gl++) {
                    uint32_t ba = w1Addr + (uint32_t)ks*4352u + (uint32_t)(nh*4+gl)*32u;
                    uint32_t bh0,bh1,bh2,bh3, bl0,bl1,bl2,bl3;
                    ldsm4t(bh0,bh1,bh2,bh3, ba);
                    ldsm4t(bl0,bl1,bl2,bl3, ba + (W1L_O - W1H_O));
#pragma unroll
                    for (int st2 = 0; st2 < 2; st2++) {
                        mma16816(acc1[st2][2*gl],   a1h[st2][ks], bh0, bh1);
                        mma16816(acc1[st2][2*gl],   a1l[st2][ks], bh0, bh1);
                        mma16816(acc1[st2][2*gl],   a1h[st2][ks], bl0, bl1);
                        mma16816(acc1[st2][2*gl+1], a1h[st2][ks], bh2, bh3);
                        mma16816(acc1[st2][2*gl+1], a1l[st2][ks], bh2, bh3);
                        mma16816(acc1[st2][2*gl+1], a1h[st2][ks], bl2, bl3);
                    }
                }
            // per k-block: GELU + pack to A-frags (D->A reuse), then MMA2 partial
#pragma unroll
            for (int kbl = 0; kbl < 4; kbl++) {
                uint32_t afh[2][4], afl[2][4];
#pragma unroll
                for (int st2 = 0; st2 < 2; st2++)
#pragma unroll
                    for (int half = 0; half < 2; half++) {
                        const int t = 2*kbl + half;
                        float v0 = gelu_exact(acc1[st2][t][0]);
                        float v1 = gelu_exact(acc1[st2][t][1]);
                        float v2 = gelu_exact(acc1[st2][t][2]);
                        float v3 = gelu_exact(acc1[st2][t][3]);
                        u64 p01 = pk2(v0,v1), p23 = pk2(v2,v3);
                        sP[st2][0] = fadd2(sP[st2][0], p01);
                        qP[st2][0] = ffma2(p01, p01, qP[st2][0]);
                        sP[st2][1] = fadd2(sP[st2][1], p23);
                        qP[st2][1] = ffma2(p23, p23, qP[st2][1]);
                        __nv_bfloat162 H0 = __floats2bfloat162_rn(v0, v1);
                        __nv_bfloat162 L0 = __floats2bfloat162_rn(v0 - __low2float(H0), v1 - __high2float(H0));
                        __nv_bfloat162 H1 = __floats2bfloat162_rn(v2, v3);
                        __nv_bfloat162 L1 = __floats2bfloat162_rn(v2 - __low2float(H1), v3 - __high2float(H1));
                        afh[st2][2*half]     = *(uint32_t*)&H0;   // rows dm,   k-half 'half'
                        afh[st2][2*half + 1] = *(uint32_t*)&H1;   // rows dm+8
                        afl[st2][2*half]     = *(uint32_t*)&L0;
                        afl[st2][2*half + 1] = *(uint32_t*)&L1;
                    }
                const uint32_t ks2 = (uint32_t)(nh*4 + kbl);
#pragma unroll
                for (int jt2 = 0; jt2 < 8; jt2++) {
                    uint32_t bh0,bh1,bh2,bh3, bl0,bl1,bl2,bl3;
                    uint32_t ba = bAddr + ks2*16u*272u + (uint32_t)jt2*32u;
                    ldsm4t(bh0,bh1,bh2,bh3, ba);
                    ldsm4t(bl0,bl1,bl2,bl3, ba + (W2L_O - W2H_O));
#pragma unroll
                    for (int st2 = 0; st2 < 2; st2++) {
                        mma16816(acc[st2][2*jt2],   afh[st2], bh0, bh1);
                        mma16816(acc[st2][2*jt2],   afl[st2], bh0, bh1);
                        mma16816(acc[st2][2*jt2],   afh[st2], bl0, bl1);
                        mma16816(acc[st2][2*jt2+1], afh[st2], bh2, bh3);
                        mma16816(acc[st2][2*jt2+1], afl[st2], bh2, bh3);
                        mma16816(acc[st2][2*jt2+1], afh[st2], bl2, bl3);
                    }
                }
            }
        }

        // LN1 stats finalize (4-lane row groups) + broadcast to sample threads
#pragma unroll
        for (int st2 = 0; st2 < 2; st2++)
#pragma unroll
            for (int h = 0; h < 2; h++) {
                float a, b; upk2(sP[st2][h], a, b); float sum = a + b;
                upk2(qP[st2][h], a, b); float sq = a + b;
                sum += __shfl_xor_sync(0xFFFFFFFFu, sum, 1);
                sum += __shfl_xor_sync(0xFFFFFFFFu, sum, 2);
                sq  += __shfl_xor_sync(0xFFFFFFFFu, sq, 1);
                sq  += __shfl_xor_sync(0xFFFFFFFFu, sq, 2);
                float mu = sum * (1.0f/128.0f);
                float rs = rsqrtf(sq*(1.0f/128.0f) - mu*mu + 1e-5f);
                rs1v[st2][h] = rs;  bc1v[st2][h] = rs*mu;
            }
        float rs1 = 0.f, bco1 = 0.f;
        {
            const int st_s = lane >> 4, h_s = (lane >> 3) & 1, src = (lane & 7)*4;
#pragma unroll
            for (int st2 = 0; st2 < 2; st2++)
#pragma unroll
                for (int h = 0; h < 2; h++) {
                    float tr = __shfl_sync(0xFFFFFFFFu, rs1v[st2][h], src);
                    float tb = __shfl_sync(0xFFFFFFFFu, bc1v[st2][h], src);
                    if (st2 == st_s && h == h_s) { rs1 = tr; bco1 = tb; }
                }
        }
        __syncwarp();   // x-region ldsm reads done (warp-converged) before H2 overlays it

        // ---------------- H2 store (warp-private): chunk c = j/4, row = warp-local sample ----------------
#pragma unroll
        for (int st2 = 0; st2 < 2; st2++) {
#pragma unroll
            for (int t = 0; t < 16; t++) {
                const int j0 = t*8 + dj;
                const int c = j0 >> 2;                    // = 2t + (q>>1)
                const uint32_t coff = (uint32_t)((j0 & 3) << 2);
                char* cb = (c < 16) ? (h2A + c*512) : (h2B + (c-16)*512);
                *(float2*)(cb + (uint32_t)(st2*16 + dm)*16u + coff)     = make_float2(acc[st2][t][0], acc[st2][t][1]);
                *(float2*)(cb + (uint32_t)(st2*16 + dm + 8)*16u + coff) = make_float2(acc[st2][t][2], acc[st2][t][3]);
            }
        }
        __syncwarp();

        // ---------------- readback: LN1-fold -> GELU -> LN2 stats + layer 3 ----------------
        float sum2 = 0.f, sq2 = 0.f;
        u64 S0=0,S1=0,S2=0,S3=0;
        const float2* const G2C2 = (const float2*)(smc + G2C2_O);
        for (int c = 0; c < 32; c++) {
            char* cb = (c < 16) ? (h2A + c*512) : (h2B + (c-16)*512);
            float4 t4 = *(const float4*)(cb + (uint32_t)lane*16u);
            float tv[4] = {t4.x, t4.y, t4.z, t4.w};
#pragma unroll
            for (int e = 0; e < 4; e++) {
                const int row = 4*c + e;
                float2 gc = G2C2[row];
                float v = gelu_exact(rs1*tv[e] - bco1*gc.x + gc.y);
                sum2 += v; sq2 += v*v;
                const ulonglong2* w3r = (const ulonglong2*)(smf + W3G_O/4 + row*8);
                ulonglong2 wa3 = w3r[0], wb3 = w3r[1];
                u64 v2 = pk2(v,v);
                S0 = ffma2(v2, wa3.x, S0);  S1 = ffma2(v2, wa3.y, S1);
                S2 = ffma2(v2, wb3.x, S2);  S3 = ffma2(v2, wb3.y, S3);
            }
        }
        float mu2 = sum2*(1.0f/128.0f);
        float rs2 = rsqrtf(sq2*(1.0f/128.0f) - mu2*mu2 + 1e-5f);
        float bco2 = rs2*mu2;
        float sv[8];
        upk2(S0, sv[0], sv[1]); upk2(S1, sv[2], sv[3]);
        upk2(S2, sv[4], sv[5]); upk2(S3, sv[6], sv[7]);

        const float ssi = 1.0f/(1.0f + expf(-slog[it]));
        const float LO[7] = {-2.8973f,-1.7628f,-2.8973f,-3.0718f,-2.8973f,-0.0175f,-2.8973f};
        const float HI[7] = { 2.8973f, 1.7628f, 2.8973f,-0.0698f, 2.8973f, 3.7525f, 2.8973f};
#pragma unroll
        for (int jj = 0; jj < 7; jj++) {
            float dl = rs2*sv[jj] - bco2*smf[G3_O/4 + jj] + smf[C3_O/4 + jj];
            th[jj] = fminf(fmaxf(th[jj] + ssi*dl, LO[jj]), HI[jj]);
        }
        float* pa = outAng + ((size_t)(it+1)*B_TOT + s)*7;
#pragma unroll
        for (int jj = 0; jj < 7; jj++) pa[jj] = th[jj];

        __syncwarp();   // H2 reads done before next iter's x staging overwrites
    }
}

extern "C" void kernel_launch(void* const* d_in, const int* in_sizes, int n_in,
                              void* d_out, int out_size) {
    (void)in_sizes; (void)n_in; (void)out_size;
    cudaFuncSetAttribute(irm_kernel, cudaFuncAttributeMaxDynamicSharedMemorySize, SMEM_BYTES);
    irm_kernel<<<CTAS, THREADS, SMEM_BYTES>>>(
        (const float*)d_in[0], (const float*)d_in[1], (const float*)d_in[2],
        (const float*)d_in[4], (const float*)d_in[5], (const int*)d_in[6],
        (const float*)d_in[7],  (const float*)d_in[8],
        (const float*)d_in[9],  (const float*)d_in[10],
        (const float*)d_in[11], (const float*)d_in[12],
        (const float*)d_in[13], (const float*)d_in[14],
        (const float*)d_in[15], (const float*)d_in[16],
        (const float*)d_in[17],
        (float*)d_out);
}